// round 8
// baseline (speedup 1.0000x reference)
#include <cuda_runtime.h>
#include <cuda_bf16.h>
#include <cstdint>

// Problem constants
#define BB   4
#define SS   2048
#define DD   1024
#define HH   16
#define HD   64
#define BS   (BB*SS)        // 8192

__device__ __forceinline__ uint32_t smem_u32(const void* p) {
    uint32_t a;
    asm("{ .reg .u64 t; cvta.to.shared.u64 t, %1; cvt.u32.u64 %0, t; }" : "=r"(a) : "l"(p));
    return a;
}
__device__ __forceinline__ void cp16(uint32_t dst, const void* src) {
    asm volatile("cp.async.cg.shared.global [%0], [%1], 16;" :: "r"(dst), "l"(src));
}
#define CP_COMMIT() asm volatile("cp.async.commit_group;" ::: "memory")
#define CP_WAIT0()  asm volatile("cp.async.wait_group 0;" ::: "memory")

// ---------------------------------------------------------------------------
// Scratch (device globals)
// ---------------------------------------------------------------------------
__device__ __nv_bfloat16 g_xh[(size_t)BS * DD];
__device__ __nv_bfloat16 g_xl[(size_t)BS * DD];
__device__ __nv_bfloat16 g_w1h[(size_t)(3*DD) * DD]; // W_in^T  [3072,1024]
__device__ __nv_bfloat16 g_w1l[(size_t)(3*DD) * DD];
__device__ __nv_bfloat16 g_w2h[(size_t)DD * DD];     // W_out^T [1024,1024]
__device__ __nv_bfloat16 g_w2l[(size_t)DD * DD];
__device__ __nv_bfloat16 g_ph[(size_t)BS * 3 * DD];  // proj split hi (k|q|v)
__device__ __nv_bfloat16 g_pl[(size_t)BS * 3 * DD];  // proj split lo
__device__ __nv_bfloat16 g_ah[(size_t)BS * DD];      // attention out split hi
__device__ __nv_bfloat16 g_al[(size_t)BS * DD];      // attention out split lo

// ---------------------------------------------------------------------------
// Prep kernels
// ---------------------------------------------------------------------------
__global__ __launch_bounds__(256) void split_bf16(
    const float* __restrict__ src, __nv_bfloat16* __restrict__ hi,
    __nv_bfloat16* __restrict__ lo, int n4)
{
    int i = blockIdx.x * 256 + threadIdx.x;
    if (i >= n4) return;
    float4 v = ((const float4*)src)[i];
    __nv_bfloat162 h0, h1, l0, l1;
    float hx;
    hx = __bfloat162float(__float2bfloat16(v.x)); h0.x = __float2bfloat16(v.x); l0.x = __float2bfloat16(v.x - hx);
    hx = __bfloat162float(__float2bfloat16(v.y)); h0.y = __float2bfloat16(v.y); l0.y = __float2bfloat16(v.y - hx);
    hx = __bfloat162float(__float2bfloat16(v.z)); h1.x = __float2bfloat16(v.z); l1.x = __float2bfloat16(v.z - hx);
    hx = __bfloat162float(__float2bfloat16(v.w)); h1.y = __float2bfloat16(v.w); l1.y = __float2bfloat16(v.w - hx);
    ((__nv_bfloat162*)hi)[i*2+0] = h0; ((__nv_bfloat162*)hi)[i*2+1] = h1;
    ((__nv_bfloat162*)lo)[i*2+0] = l0; ((__nv_bfloat162*)lo)[i*2+1] = l1;
}

__global__ __launch_bounds__(256) void transpose_split(
    const float* __restrict__ W, __nv_bfloat16* __restrict__ th,
    __nv_bfloat16* __restrict__ tl, int K, int N)
{
    __shared__ float tile[32][33];
    int k0 = blockIdx.y * 32, n0 = blockIdx.x * 32;
    int tx = threadIdx.x, ty = threadIdx.y;   // 32 x 8
#pragma unroll
    for (int j = 0; j < 32; j += 8)
        tile[ty + j][tx] = W[(size_t)(k0 + ty + j) * N + n0 + tx];
    __syncthreads();
#pragma unroll
    for (int j = 0; j < 32; j += 8) {
        float v = tile[tx][ty + j];
        __nv_bfloat16 h = __float2bfloat16(v);
        __nv_bfloat16 l = __float2bfloat16(v - __bfloat162float(h));
        size_t o = (size_t)(n0 + ty + j) * K + k0 + tx;
        th[o] = h; tl[o] = l;
    }
}

// ---------------------------------------------------------------------------
// mma.sync helpers
// ---------------------------------------------------------------------------
__device__ __forceinline__ void ldsm_x4(uint32_t& r0, uint32_t& r1, uint32_t& r2, uint32_t& r3,
                                        uint32_t addr) {
    asm volatile("ldmatrix.sync.aligned.m8n8.x4.shared.b16 {%0,%1,%2,%3}, [%4];"
                 : "=r"(r0), "=r"(r1), "=r"(r2), "=r"(r3) : "r"(addr));
}
__device__ __forceinline__ void ldsm_x4_t(uint32_t& r0, uint32_t& r1, uint32_t& r2, uint32_t& r3,
                                          uint32_t addr) {
    asm volatile("ldmatrix.sync.aligned.m8n8.x4.trans.shared.b16 {%0,%1,%2,%3}, [%4];"
                 : "=r"(r0), "=r"(r1), "=r"(r2), "=r"(r3) : "r"(addr));
}
__device__ __forceinline__ void mma_bf16(float* d, const uint32_t* a, uint32_t b0, uint32_t b1) {
    asm volatile(
        "mma.sync.aligned.m16n8k16.row.col.f32.bf16.bf16.f32 "
        "{%0,%1,%2,%3}, {%4,%5,%6,%7}, {%8,%9}, {%0,%1,%2,%3};"
        : "+f"(d[0]), "+f"(d[1]), "+f"(d[2]), "+f"(d[3])
        : "r"(a[0]), "r"(a[1]), "r"(a[2]), "r"(a[3]), "r"(b0), "r"(b1));
}
__device__ __forceinline__ uint32_t pack_hi2(float x, float y) {
    __nv_bfloat162 t = __floats2bfloat162_rn(x, y);
    return *(uint32_t*)&t;
}
__device__ __forceinline__ uint32_t pack_lo2(float x, float y) {
    float hx = __bfloat162float(__float2bfloat16(x));
    float hy = __bfloat162float(__float2bfloat16(y));
    __nv_bfloat162 t = __floats2bfloat162_rn(x - hx, y - hy);
    return *(uint32_t*)&t;
}

// ---------------------------------------------------------------------------
// Persistent GEMM on mma.sync, 3-term split, continuous cp.async pipeline
// across tiles, one __syncthreads per chunk, 2 CTAs/SM.
// ---------------------------------------------------------------------------
#define PA 40
#define STG (4 * 128 * PA)   // bf16 elems per stage (20480)

__global__ __launch_bounds__(256, 2) void gemm_mma(
    const __nv_bfloat16* __restrict__ Ah, const __nv_bfloat16* __restrict__ Al,
    const __nv_bfloat16* __restrict__ Bh, const __nv_bfloat16* __restrict__ Bl,
    const float* __restrict__ bias,
    float* __restrict__ C, __nv_bfloat16* __restrict__ Ch, __nv_bfloat16* __restrict__ Cl,
    int M, int N, int K, int ntn)
{
    extern __shared__ __nv_bfloat16 sg[];   // 2 * STG
    const uint32_t uBase = smem_u32(sg);

    const int tid  = threadIdx.x;
    const int wid  = tid >> 5;
    const int lane = tid & 31;
    const int wrow = wid & 3;
    const int wcol = wid >> 2;

    const int a_row = wrow * 32 + (lane & 7) + ((lane >> 3) & 1) * 8;
    const int a_k   = (lane >> 4) * 8;
    const int b_row = wcol * 64 + (lane >> 4) * 8 + (lane & 7);
    const int b_k   = ((lane >> 3) & 1) * 8;

    const int ntiles  = (M >> 7) * ntn;
    const int nchunks = K >> 5;

    auto load_chunk = [&](int t, int kc, int buf) {
        const int m0 = (t / ntn) << 7;
        const int n0 = (t % ntn) << 7;
        const int k0 = kc << 5;
        const __nv_bfloat16* gs0 = Ah + (size_t)m0 * K + k0;
        const __nv_bfloat16* gs1 = Al + (size_t)m0 * K + k0;
        const __nv_bfloat16* gs2 = Bh + (size_t)n0 * K + k0;
        const __nv_bfloat16* gs3 = Bl + (size_t)n0 * K + k0;
        const uint32_t sb = uBase + buf * (STG * 2);
        // 512 vectors per (tile-chunk) pair of A/B hi/lo: 2048 total / 256 thr
#pragma unroll
        for (int v = tid; v < 2048; v += 256) {
            int tt = v >> 9, idx = v & 511;
            int r = idx >> 2, c = idx & 3;
            const __nv_bfloat16* g = (tt == 0) ? gs0 : (tt == 1) ? gs1 : (tt == 2) ? gs2 : gs3;
            cp16(sb + (tt * (128 * PA) + r * PA + c * 8) * 2,
                 g + (size_t)r * K + c * 8);
        }
    };

    // prologue: first chunk of first tile
    int lt = blockIdx.x, lk = 0;
    if (lt < ntiles) { load_chunk(lt, lk, 0); CP_COMMIT(); lk = 1; }
    int gbuf = 0;

    for (int tile = blockIdx.x; tile < ntiles; tile += gridDim.x) {
        float acc[2][8][4];
#pragma unroll
        for (int i = 0; i < 2; i++)
#pragma unroll
            for (int j = 0; j < 8; j++)
#pragma unroll
                for (int v = 0; v < 4; v++) acc[i][j][v] = 0.f;

        for (int kc = 0; kc < nchunks; ++kc) {
            CP_WAIT0();
            __syncthreads();
            if (lt < ntiles) {
                load_chunk(lt, lk, gbuf ^ 1);
                CP_COMMIT();
                if (++lk == nchunks) { lk = 0; lt += gridDim.x; }
            }

            const uint32_t s0 = uBase + gbuf * (STG * 2);
            const uint32_t tAh = s0;
            const uint32_t tAl = s0 + (128 * PA) * 2;
            const uint32_t tBh = s0 + 2 * (128 * PA) * 2;
            const uint32_t tBl = s0 + 3 * (128 * PA) * 2;

#pragma unroll
            for (int ks = 0; ks < 2; ks++) {
                uint32_t ah[2][4], al2[2][4];
#pragma unroll
                for (int mi = 0; mi < 2; mi++) {
                    uint32_t off = 2 * ((a_row + mi * 16) * PA + ks * 16 + a_k);
                    ldsm_x4(ah[mi][0], ah[mi][1], ah[mi][2], ah[mi][3], tAh + off);
                    ldsm_x4(al2[mi][0], al2[mi][1], al2[mi][2], al2[mi][3], tAl + off);
                }
#pragma unroll
                for (int j = 0; j < 4; j++) {
                    uint32_t off = 2 * ((b_row + j * 16) * PA + ks * 16 + b_k);
                    uint32_t bh0, bh1, bh2, bh3, bl0, bl1, bl2, bl3;
                    ldsm_x4(bh0, bh1, bh2, bh3, tBh + off);
                    ldsm_x4(bl0, bl1, bl2, bl3, tBl + off);
#pragma unroll
                    for (int mi = 0; mi < 2; mi++) {
                        mma_bf16(acc[mi][2*j],   ah[mi],  bh0, bh1);
                        mma_bf16(acc[mi][2*j+1], ah[mi],  bh2, bh3);
                        mma_bf16(acc[mi][2*j],   ah[mi],  bl0, bl1);
                        mma_bf16(acc[mi][2*j+1], ah[mi],  bl2, bl3);
                        mma_bf16(acc[mi][2*j],   al2[mi], bh0, bh1);
                        mma_bf16(acc[mi][2*j+1], al2[mi], bh2, bh3);
                    }
                }
            }
            gbuf ^= 1;
        }

        // epilogue (overlapped with next tile's chunk-0 load already in flight)
        const int m0 = (tile / ntn) << 7;
        const int n0 = (tile % ntn) << 7;
        const int row0 = m0 + wrow * 32 + (lane >> 2);
        const int colb = n0 + wcol * 64 + (lane & 3) * 2;
#pragma unroll
        for (int mi = 0; mi < 2; mi++) {
#pragma unroll
            for (int nj = 0; nj < 8; nj++) {
                int c = colb + nj * 8;
                float2 bv = *(const float2*)(bias + c);
                float o00 = acc[mi][nj][0] + bv.x, o01 = acc[mi][nj][1] + bv.y;
                float o10 = acc[mi][nj][2] + bv.x, o11 = acc[mi][nj][3] + bv.y;
                size_t r0o = (size_t)(row0 + mi * 16) * N + c;
                size_t r1o = (size_t)(row0 + mi * 16 + 8) * N + c;
                if (Ch) {
                    *(uint32_t*)(Ch + r0o) = pack_hi2(o00, o01);
                    *(uint32_t*)(Cl + r0o) = pack_lo2(o00, o01);
                    *(uint32_t*)(Ch + r1o) = pack_hi2(o10, o11);
                    *(uint32_t*)(Cl + r1o) = pack_lo2(o10, o11);
                } else {
                    *(float2*)(C + r0o) = make_float2(o00, o01);
                    *(float2*)(C + r1o) = make_float2(o10, o11);
                }
            }
        }
    }
}

// ---------------------------------------------------------------------------
// Flash-attention on mma.sync. 128-row tiles, cp.async double-buffered K/V,
// single sync per iteration, heavy q-blocks scheduled first.
// ---------------------------------------------------------------------------
#define PT 72
#define AT (128 * PT)      // one tile in bf16 elems (9216)
#define A_SMEM ((2 + 8) * AT * 2)   // 184320 B

__global__ __launch_bounds__(256) void attn_mma(
    const __nv_bfloat16* __restrict__ ph, const __nv_bfloat16* __restrict__ pl,
    __nv_bfloat16* __restrict__ oh, __nv_bfloat16* __restrict__ ol)
{
    extern __shared__ __nv_bfloat16 sb[];
    const uint32_t uBase = smem_u32(sb);
    const uint32_t uQh = uBase, uQl = uBase + AT * 2;

    const int qb = gridDim.x - 1 - blockIdx.x;   // heavy blocks first
    const int bh = blockIdx.y;
    const int b = bh / HH, h = bh % HH;
    const int tid = threadIdx.x, w = tid >> 5, lane = tid & 31;
    const int quad = lane & 3, trow = lane >> 2;

    const size_t rowstride = 3 * DD;
    const size_t rbase = (size_t)b * SS * rowstride;
    const int koff = h * HD, qoff = DD + h * HD, voff = 2 * DD + h * HD;

    // Q copy (hi+lo)
#pragma unroll
    for (int i = tid; i < 2048; i += 256) {
        int t = i >> 10, idx = i & 1023;
        int r = idx >> 3, c = idx & 7;
        const __nv_bfloat16* src = (t ? pl : ph) + rbase + (size_t)(qb * 128 + r) * rowstride + qoff + c * 8;
        cp16(uBase + (t * AT + r * PT + c * 8) * 2, src);
    }

    auto load_kv = [&](int kb, int buf) {
        const uint32_t sbs = uBase + (2 * AT + buf * 4 * AT) * 2;
#pragma unroll
        for (int i = tid; i < 4096; i += 256) {
            int t = i >> 10, idx = i & 1023;
            int r = idx >> 3, c = idx & 7;
            const __nv_bfloat16* base = (t & 1) ? pl : ph;
            int off = (t >= 2) ? voff : koff;
            cp16(sbs + (t * AT + r * PT + c * 8) * 2,
                 base + rbase + (size_t)(kb * 128 + r) * rowstride + off + c * 8);
        }
    };

    load_kv(0, 0);
    CP_COMMIT();

    float acc_o[8][4];
#pragma unroll
    for (int j = 0; j < 8; j++)
#pragma unroll
        for (int v = 0; v < 4; v++) acc_o[j][v] = 0.f;
    float m0 = -1e30f, m1 = -1e30f, l0 = 0.f, l1 = 0.f;

    for (int kb = 0; kb <= qb; ++kb) {
        const int buf = kb & 1;
        CP_WAIT0();
        __syncthreads();
        if (kb < qb) {
            load_kv(kb + 1, buf ^ 1);
            CP_COMMIT();
        }
        const uint32_t s0 = uBase + (2 * AT + buf * 4 * AT) * 2;
        const uint32_t uKh = s0, uKl = s0 + AT * 2;
        const uint32_t uVh = s0 + 2 * AT * 2, uVl = s0 + 3 * AT * 2;

        // ---- S = Q @ K^T: fragments loaded once, 3 split terms ----
        float s[16][4];
#pragma unroll
        for (int j = 0; j < 16; j++)
#pragma unroll
            for (int v = 0; v < 4; v++) s[j][v] = 0.f;

#pragma unroll
        for (int kc = 0; kc < 4; kc++) {
            uint32_t qfh[4], qfl[4];
            uint32_t aoff = 2 * ((w * 16 + (lane & 15)) * PT + kc * 16 + (lane >> 4) * 8);
            ldsm_x4(qfh[0], qfh[1], qfh[2], qfh[3], uQh + aoff);
            ldsm_x4(qfl[0], qfl[1], qfl[2], qfl[3], uQl + aoff);
#pragma unroll
            for (int ntp = 0; ntp < 8; ntp++) {
                uint32_t boff = 2 * ((ntp * 16 + (lane & 15)) * PT + kc * 16 + (lane >> 4) * 8);
                uint32_t kh0, kh1, kh2, kh3, kl0, kl1, kl2, kl3;
                ldsm_x4(kh0, kh1, kh2, kh3, uKh + boff);
                ldsm_x4(kl0, kl1, kl2, kl3, uKl + boff);
                mma_bf16(s[2*ntp],   qfh, kh0, kh2);
                mma_bf16(s[2*ntp+1], qfh, kh1, kh3);
                mma_bf16(s[2*ntp],   qfh, kl0, kl2);
                mma_bf16(s[2*ntp+1], qfh, kl1, kl3);
                mma_bf16(s[2*ntp],   qfl, kh0, kh2);
                mma_bf16(s[2*ntp+1], qfl, kh1, kh3);
            }
        }

        // scale 1/8
#pragma unroll
        for (int nt = 0; nt < 16; nt++) {
            s[nt][0] *= 0.125f; s[nt][1] *= 0.125f;
            s[nt][2] *= 0.125f; s[nt][3] *= 0.125f;
        }

        // causal mask (diagonal block only)
        if (kb == qb) {
            const int rl0 = w * 16 + trow;
#pragma unroll
            for (int nt = 0; nt < 16; nt++) {
                int c0 = nt * 8 + 2 * quad;
                if (c0 > rl0)     s[nt][0] = -1e30f;
                if (c0 + 1 > rl0) s[nt][1] = -1e30f;
                if (c0 > rl0 + 8)     s[nt][2] = -1e30f;
                if (c0 + 1 > rl0 + 8) s[nt][3] = -1e30f;
            }
        }

        // ---- online softmax ----
        float mx0 = -1e30f, mx1 = -1e30f;
#pragma unroll
        for (int nt = 0; nt < 16; nt++) {
            mx0 = fmaxf(mx0, fmaxf(s[nt][0], s[nt][1]));
            mx1 = fmaxf(mx1, fmaxf(s[nt][2], s[nt][3]));
        }
        mx0 = fmaxf(mx0, __shfl_xor_sync(0xffffffffu, mx0, 1));
        mx0 = fmaxf(mx0, __shfl_xor_sync(0xffffffffu, mx0, 2));
        mx1 = fmaxf(mx1, __shfl_xor_sync(0xffffffffu, mx1, 1));
        mx1 = fmaxf(mx1, __shfl_xor_sync(0xffffffffu, mx1, 2));
        float m0n = fmaxf(m0, mx0), m1n = fmaxf(m1, mx1);
        float al0 = __expf(m0 - m0n), al1 = __expf(m1 - m1n);
        m0 = m0n; m1 = m1n;

        float sum0 = 0.f, sum1 = 0.f;
#pragma unroll
        for (int nt = 0; nt < 16; nt++) {
            s[nt][0] = __expf(s[nt][0] - m0); sum0 += s[nt][0];
            s[nt][1] = __expf(s[nt][1] - m0); sum0 += s[nt][1];
            s[nt][2] = __expf(s[nt][2] - m1); sum1 += s[nt][2];
            s[nt][3] = __expf(s[nt][3] - m1); sum1 += s[nt][3];
        }
        sum0 += __shfl_xor_sync(0xffffffffu, sum0, 1);
        sum0 += __shfl_xor_sync(0xffffffffu, sum0, 2);
        sum1 += __shfl_xor_sync(0xffffffffu, sum1, 1);
        sum1 += __shfl_xor_sync(0xffffffffu, sum1, 2);
        l0 = l0 * al0 + sum0;
        l1 = l1 * al1 + sum1;

#pragma unroll
        for (int j = 0; j < 8; j++) {
            acc_o[j][0] *= al0; acc_o[j][1] *= al0;
            acc_o[j][2] *= al1; acc_o[j][3] *= al1;
        }

        // ---- O += P @ V (split P and V) ----
#pragma unroll
        for (int kc = 0; kc < 8; kc++) {
            uint32_t pha[4], pla[4];
            pha[0] = pack_hi2(s[2*kc][0],   s[2*kc][1]);
            pha[1] = pack_hi2(s[2*kc][2],   s[2*kc][3]);
            pha[2] = pack_hi2(s[2*kc+1][0], s[2*kc+1][1]);
            pha[3] = pack_hi2(s[2*kc+1][2], s[2*kc+1][3]);
            pla[0] = pack_lo2(s[2*kc][0],   s[2*kc][1]);
            pla[1] = pack_lo2(s[2*kc][2],   s[2*kc][3]);
            pla[2] = pack_lo2(s[2*kc+1][0], s[2*kc+1][1]);
            pla[3] = pack_lo2(s[2*kc+1][2], s[2*kc+1][3]);
#pragma unroll
            for (int ht = 0; ht < 4; ht++) {
                uint32_t vh0, vh1, vh2, vh3, vl0, vl1, vl2, vl3;
                uint32_t off = 2 * ((kc * 16 + (lane & 15)) * PT + ht * 16 + (lane >> 4) * 8);
                ldsm_x4_t(vh0, vh1, vh2, vh3, uVh + off);
                ldsm_x4_t(vl0, vl1, vl2, vl3, uVl + off);
                mma_bf16(acc_o[2*ht],   pha, vh0, vh1);
                mma_bf16(acc_o[2*ht+1], pha, vh2, vh3);
                mma_bf16(acc_o[2*ht],   pha, vl0, vl1);
                mma_bf16(acc_o[2*ht+1], pha, vl2, vl3);
                mma_bf16(acc_o[2*ht],   pla, vh0, vh1);
                mma_bf16(acc_o[2*ht+1], pla, vh2, vh3);
            }
        }
    }

    // normalize and write split-bf16 output
    const float inv0 = 1.f / l0, inv1 = 1.f / l1;
    const size_t grow0 = (size_t)(b * SS + qb * 128 + w * 16 + trow);
    const size_t grow1 = grow0 + 8;
#pragma unroll
    for (int j = 0; j < 8; j++) {
        int c = h * HD + j * 8 + 2 * quad;
        float o00 = acc_o[j][0] * inv0, o01 = acc_o[j][1] * inv0;
        float o10 = acc_o[j][2] * inv1, o11 = acc_o[j][3] * inv1;
        *(uint32_t*)(oh + grow0 * DD + c) = pack_hi2(o00, o01);
        *(uint32_t*)(ol + grow0 * DD + c) = pack_lo2(o00, o01);
        *(uint32_t*)(oh + grow1 * DD + c) = pack_hi2(o10, o11);
        *(uint32_t*)(ol + grow1 * DD + c) = pack_lo2(o10, o11);
    }
}

// ---------------------------------------------------------------------------
extern "C" void kernel_launch(void* const* d_in, const int* in_sizes, int n_in,
                              void* d_out, int out_size)
{
    const float* x     = (const float*)d_in[0];
    const float* W_in  = (const float*)d_in[1];
    const float* b_in  = (const float*)d_in[2];
    const float* W_out = (const float*)d_in[3];
    const float* b_out = (const float*)d_in[4];
    float* out = (float*)d_out;

    __nv_bfloat16 *xh, *xl, *w1h, *w1l, *w2h, *w2l, *ph, *pl, *ah, *al;
    cudaGetSymbolAddress((void**)&xh, g_xh);
    cudaGetSymbolAddress((void**)&xl, g_xl);
    cudaGetSymbolAddress((void**)&w1h, g_w1h);
    cudaGetSymbolAddress((void**)&w1l, g_w1l);
    cudaGetSymbolAddress((void**)&w2h, g_w2h);
    cudaGetSymbolAddress((void**)&w2l, g_w2l);
    cudaGetSymbolAddress((void**)&ph, g_ph);
    cudaGetSymbolAddress((void**)&pl, g_pl);
    cudaGetSymbolAddress((void**)&ah, g_ah);
    cudaGetSymbolAddress((void**)&al, g_al);

    const int gemm_smem = 2 * STG * (int)sizeof(__nv_bfloat16);   // 81920
    cudaFuncSetAttribute(gemm_mma, cudaFuncAttributeMaxDynamicSharedMemorySize, gemm_smem);
    cudaFuncSetAttribute(attn_mma, cudaFuncAttributeMaxDynamicSharedMemorySize, A_SMEM);

    // prep
    split_bf16<<<(BS * DD / 4 + 255) / 256, 256>>>(x, xh, xl, BS * DD / 4);
    transpose_split<<<dim3(3 * DD / 32, DD / 32), dim3(32, 8)>>>(W_in, w1h, w1l, DD, 3 * DD);
    transpose_split<<<dim3(DD / 32, DD / 32), dim3(32, 8)>>>(W_out, w2h, w2l, DD, DD);

    const int PGRID = 304;   // 2 per SM on 152 SMs

    // 1) QKV projection -> split bf16 proj  (persistent)
    gemm_mma<<<PGRID, 256, gemm_smem>>>(
        xh, xl, w1h, w1l, b_in, nullptr, ph, pl, BS, 3 * DD, DD, 3 * DD / 128);

    // 2) attention
    {
        dim3 grid(SS / 128, BB * HH);
        attn_mma<<<grid, 256, A_SMEM>>>(ph, pl, ah, al);
    }

    // 3) output projection -> fp32 out  (persistent)
    gemm_mma<<<PGRID, 256, gemm_smem>>>(
        ah, al, w2h, w2l, b_out, out, nullptr, nullptr, BS, DD, DD, DD / 128);
}

// round 9
// speedup vs baseline: 1.4472x; 1.4472x over previous
#include <cuda_runtime.h>
#include <cuda_fp16.h>
#include <cstdint>

// Problem constants
#define BB   4
#define SS   2048
#define DD   1024
#define HH   16
#define HD   64
#define BS   (BB*SS)        // 8192

__device__ __forceinline__ uint32_t smem_u32(const void* p) {
    uint32_t a;
    asm("{ .reg .u64 t; cvta.to.shared.u64 t, %1; cvt.u32.u64 %0, t; }" : "=r"(a) : "l"(p));
    return a;
}
__device__ __forceinline__ void cp16(uint32_t dst, const void* src) {
    asm volatile("cp.async.cg.shared.global [%0], [%1], 16;" :: "r"(dst), "l"(src));
}
#define CP_COMMIT() asm volatile("cp.async.commit_group;" ::: "memory")
#define CP_WAIT0()  asm volatile("cp.async.wait_group 0;" ::: "memory")

// ---------------------------------------------------------------------------
// Scratch (device globals) — one-sided fp16 split scheme:
//   activations split hi+lo, weights / K / V single fp16.
// ---------------------------------------------------------------------------
__device__ __half g_xh[(size_t)BS * DD];
__device__ __half g_xl[(size_t)BS * DD];
__device__ __half g_w1[(size_t)(3*DD) * DD];   // W_in^T  [3072,1024] fp16
__device__ __half g_w2[(size_t)DD * DD];       // W_out^T [1024,1024] fp16
__device__ __half g_ph[(size_t)BS * 3 * DD];   // proj hi (k|q|v)
__device__ __half g_pl[(size_t)BS * 3 * DD];   // proj lo (used for Q side only)
__device__ __half g_ah[(size_t)BS * DD];       // attention out hi
__device__ __half g_al[(size_t)BS * DD];       // attention out lo

// ---------------------------------------------------------------------------
// Prep kernels
// ---------------------------------------------------------------------------
__global__ __launch_bounds__(256) void split_fp16(
    const float* __restrict__ src, __half* __restrict__ hi,
    __half* __restrict__ lo, int n4)
{
    int i = blockIdx.x * 256 + threadIdx.x;
    if (i >= n4) return;
    float4 v = ((const float4*)src)[i];
    float hx, hy, hz, hw;
    hx = __half2float(__float2half_rn(v.x));
    hy = __half2float(__float2half_rn(v.y));
    hz = __half2float(__float2half_rn(v.z));
    hw = __half2float(__float2half_rn(v.w));
    ((__half2*)hi)[i*2+0] = __floats2half2_rn(v.x, v.y);
    ((__half2*)hi)[i*2+1] = __floats2half2_rn(v.z, v.w);
    ((__half2*)lo)[i*2+0] = __floats2half2_rn(v.x - hx, v.y - hy);
    ((__half2*)lo)[i*2+1] = __floats2half2_rn(v.z - hz, v.w - hw);
}

__global__ __launch_bounds__(256) void transpose_fp16(
    const float* __restrict__ W, __half* __restrict__ wt, int K, int N)
{
    __shared__ float tile[32][33];
    int k0 = blockIdx.y * 32, n0 = blockIdx.x * 32;
    int tx = threadIdx.x, ty = threadIdx.y;   // 32 x 8
#pragma unroll
    for (int j = 0; j < 32; j += 8)
        tile[ty + j][tx] = W[(size_t)(k0 + ty + j) * N + n0 + tx];
    __syncthreads();
#pragma unroll
    for (int j = 0; j < 32; j += 8)
        wt[(size_t)(n0 + ty + j) * K + k0 + tx] = __float2half_rn(tile[tx][ty + j]);
}

// ---------------------------------------------------------------------------
// mma.sync helpers (fp16 inputs, fp32 accumulate)
// ---------------------------------------------------------------------------
__device__ __forceinline__ void ldsm_x4(uint32_t& r0, uint32_t& r1, uint32_t& r2, uint32_t& r3,
                                        uint32_t addr) {
    asm volatile("ldmatrix.sync.aligned.m8n8.x4.shared.b16 {%0,%1,%2,%3}, [%4];"
                 : "=r"(r0), "=r"(r1), "=r"(r2), "=r"(r3) : "r"(addr));
}
__device__ __forceinline__ void ldsm_x4_t(uint32_t& r0, uint32_t& r1, uint32_t& r2, uint32_t& r3,
                                          uint32_t addr) {
    asm volatile("ldmatrix.sync.aligned.m8n8.x4.trans.shared.b16 {%0,%1,%2,%3}, [%4];"
                 : "=r"(r0), "=r"(r1), "=r"(r2), "=r"(r3) : "r"(addr));
}
__device__ __forceinline__ void mma_f16(float* d, const uint32_t* a, uint32_t b0, uint32_t b1) {
    asm volatile(
        "mma.sync.aligned.m16n8k16.row.col.f32.f16.f16.f32 "
        "{%0,%1,%2,%3}, {%4,%5,%6,%7}, {%8,%9}, {%0,%1,%2,%3};"
        : "+f"(d[0]), "+f"(d[1]), "+f"(d[2]), "+f"(d[3])
        : "r"(a[0]), "r"(a[1]), "r"(a[2]), "r"(a[3]), "r"(b0), "r"(b1));
}
__device__ __forceinline__ uint32_t pack_hi2(float x, float y) {
    __half2 t = __floats2half2_rn(x, y);
    return *(uint32_t*)&t;
}
__device__ __forceinline__ uint32_t pack_lo2(float x, float y) {
    float hx = __half2float(__float2half_rn(x));
    float hy = __half2float(__float2half_rn(y));
    __half2 t = __floats2half2_rn(x - hx, y - hy);
    return *(uint32_t*)&t;
}

// ---------------------------------------------------------------------------
// GEMM on mma.sync: C = (Ah+Al) @ B^T + bias.  A split fp16, B single fp16.
// 128x128 tile, BK=32, cp.async double buffer, 2 CTAs/SM.
// ---------------------------------------------------------------------------
#define PA 40
#define STG (3 * 128 * PA)   // fp16 elems per stage (Ah | Al | B)

__global__ __launch_bounds__(256, 2) void gemm_mma(
    const __half* __restrict__ Ah, const __half* __restrict__ Al,
    const __half* __restrict__ Bw,
    const float* __restrict__ bias,
    float* __restrict__ C, __half* __restrict__ Ch, __half* __restrict__ Cl,
    int M, int N, int K)
{
    extern __shared__ __half sg[];   // 2 * STG
    const uint32_t uBase = smem_u32(sg);

    const int tid  = threadIdx.x;
    const int wid  = tid >> 5;
    const int lane = tid & 31;
    const int wrow = wid & 3;
    const int wcol = wid >> 2;
    const int m0 = blockIdx.y * 128;
    const int n0 = blockIdx.x * 128;

    const int a_row = wrow * 32 + (lane & 7) + ((lane >> 3) & 1) * 8;
    const int a_k   = (lane >> 4) * 8;
    const int b_row = wcol * 64 + (lane >> 4) * 8 + (lane & 7);
    const int b_k   = ((lane >> 3) & 1) * 8;

    const __half* gsrc[3] = {
        Ah + (size_t)m0 * K, Al + (size_t)m0 * K, Bw + (size_t)n0 * K };

    auto load_stage = [&](int kc, int buf) {
        const int k0 = kc << 5;
        const uint32_t sb = uBase + buf * (STG * 2);
#pragma unroll
        for (int v = tid; v < 1536; v += 256) {
            int t = v >> 9, idx = v & 511;
            int r = idx >> 2, c = idx & 3;
            cp16(sb + (t * (128 * PA) + r * PA + c * 8) * 2,
                 gsrc[t] + (size_t)r * K + k0 + c * 8);
        }
    };

    float acc[2][8][4];
#pragma unroll
    for (int i = 0; i < 2; i++)
#pragma unroll
        for (int j = 0; j < 8; j++)
#pragma unroll
            for (int v = 0; v < 4; v++) acc[i][j][v] = 0.f;

    const int nchunks = K >> 5;
    load_stage(0, 0);
    CP_COMMIT();

    for (int kc = 0; kc < nchunks; ++kc) {
        const int buf = kc & 1;
        CP_WAIT0();
        __syncthreads();
        if (kc + 1 < nchunks) {
            load_stage(kc + 1, buf ^ 1);
            CP_COMMIT();
        }
        const uint32_t s0 = uBase + buf * (STG * 2);
        const uint32_t tAh = s0;
        const uint32_t tAl = s0 + (128 * PA) * 2;
        const uint32_t tB  = s0 + 2 * (128 * PA) * 2;

#pragma unroll
        for (int ks = 0; ks < 2; ks++) {
            uint32_t ah[2][4], al2[2][4];
#pragma unroll
            for (int mi = 0; mi < 2; mi++) {
                uint32_t off = 2 * ((a_row + mi * 16) * PA + ks * 16 + a_k);
                ldsm_x4(ah[mi][0], ah[mi][1], ah[mi][2], ah[mi][3], tAh + off);
                ldsm_x4(al2[mi][0], al2[mi][1], al2[mi][2], al2[mi][3], tAl + off);
            }
#pragma unroll
            for (int j = 0; j < 4; j++) {
                uint32_t off = 2 * ((b_row + j * 16) * PA + ks * 16 + b_k);
                uint32_t b0, b1, b2, b3;
                ldsm_x4(b0, b1, b2, b3, tB + off);
#pragma unroll
                for (int mi = 0; mi < 2; mi++) {
                    mma_f16(acc[mi][2*j],   ah[mi],  b0, b1);
                    mma_f16(acc[mi][2*j+1], ah[mi],  b2, b3);
                    mma_f16(acc[mi][2*j],   al2[mi], b0, b1);
                    mma_f16(acc[mi][2*j+1], al2[mi], b2, b3);
                }
            }
        }
        __syncthreads();
    }

    const int row0 = m0 + wrow * 32 + (lane >> 2);
    const int colb = n0 + wcol * 64 + (lane & 3) * 2;
#pragma unroll
    for (int mi = 0; mi < 2; mi++) {
#pragma unroll
        for (int nj = 0; nj < 8; nj++) {
            int c = colb + nj * 8;
            float2 bv = *(const float2*)(bias + c);
            float o00 = acc[mi][nj][0] + bv.x, o01 = acc[mi][nj][1] + bv.y;
            float o10 = acc[mi][nj][2] + bv.x, o11 = acc[mi][nj][3] + bv.y;
            size_t r0o = (size_t)(row0 + mi * 16) * N + c;
            size_t r1o = (size_t)(row0 + mi * 16 + 8) * N + c;
            if (Ch) {
                *(uint32_t*)(Ch + r0o) = pack_hi2(o00, o01);
                *(uint32_t*)(Cl + r0o) = pack_lo2(o00, o01);
                *(uint32_t*)(Ch + r1o) = pack_hi2(o10, o11);
                *(uint32_t*)(Cl + r1o) = pack_lo2(o10, o11);
            } else {
                *(float2*)(C + r0o) = make_float2(o00, o01);
                *(float2*)(C + r1o) = make_float2(o10, o11);
            }
        }
    }
}

// ---------------------------------------------------------------------------
// Flash-attention: Q split fp16 (hi+lo), K and V single fp16,
// P split fp16 from registers. 128-row tiles, cp.async double-buffered K/V.
// ---------------------------------------------------------------------------
#define PT 72
#define AT (128 * PT)      // one tile in fp16 elems (9216)
// smem: Qh | Ql | stage0 (K|V) | stage1 (K|V) = 6 tiles
#define A_SMEM (6 * AT * 2)   // 110592 B

__global__ __launch_bounds__(256) void attn_mma(
    const __half* __restrict__ ph, const __half* __restrict__ pl,
    __half* __restrict__ oh, __half* __restrict__ ol)
{
    extern __shared__ __half sb[];
    const uint32_t uBase = smem_u32(sb);
    const uint32_t uQh = uBase, uQl = uBase + AT * 2;

    const int qb = gridDim.x - 1 - blockIdx.x;   // heavy blocks first
    const int bh = blockIdx.y;
    const int b = bh / HH, h = bh % HH;
    const int tid = threadIdx.x, w = tid >> 5, lane = tid & 31;
    const int quad = lane & 3, trow = lane >> 2;

    const size_t rowstride = 3 * DD;
    const size_t rbase = (size_t)b * SS * rowstride;
    const int koff = h * HD, qoff = DD + h * HD, voff = 2 * DD + h * HD;

    // Q copy (hi+lo): 2 tiles x 128 rows x 8 uint4
#pragma unroll
    for (int i = tid; i < 2048; i += 256) {
        int t = i >> 10, idx = i & 1023;
        int r = idx >> 3, c = idx & 7;
        const __half* src = (t ? pl : ph) + rbase + (size_t)(qb * 128 + r) * rowstride + qoff + c * 8;
        cp16(uBase + (t * AT + r * PT + c * 8) * 2, src);
    }

    // KV loader: K (hi only) and V (hi only) tiles
    auto load_kv = [&](int kb, int buf) {
        const uint32_t sbs = uBase + (2 * AT + buf * 2 * AT) * 2;
#pragma unroll
        for (int i = tid; i < 2048; i += 256) {
            int t = i >> 10, idx = i & 1023;
            int r = idx >> 3, c = idx & 7;
            int off = t ? voff : koff;
            cp16(sbs + (t * AT + r * PT + c * 8) * 2,
                 ph + rbase + (size_t)(kb * 128 + r) * rowstride + off + c * 8);
        }
    };

    load_kv(0, 0);
    CP_COMMIT();

    float acc_o[8][4];
#pragma unroll
    for (int j = 0; j < 8; j++)
#pragma unroll
        for (int v = 0; v < 4; v++) acc_o[j][v] = 0.f;
    float m0 = -1e30f, m1 = -1e30f, l0 = 0.f, l1 = 0.f;

    for (int kb = 0; kb <= qb; ++kb) {
        const int buf = kb & 1;
        CP_WAIT0();
        __syncthreads();
        if (kb < qb) {
            load_kv(kb + 1, buf ^ 1);
            CP_COMMIT();
        }
        const uint32_t s0 = uBase + (2 * AT + buf * 2 * AT) * 2;
        const uint32_t uK = s0, uV = s0 + AT * 2;

        // ---- S = Q @ K^T : Q hi+lo vs single K ----
        float s[16][4];
#pragma unroll
        for (int j = 0; j < 16; j++)
#pragma unroll
            for (int v = 0; v < 4; v++) s[j][v] = 0.f;

#pragma unroll
        for (int kc = 0; kc < 4; kc++) {
            uint32_t qfh[4], qfl[4];
            uint32_t aoff = 2 * ((w * 16 + (lane & 15)) * PT + kc * 16 + (lane >> 4) * 8);
            ldsm_x4(qfh[0], qfh[1], qfh[2], qfh[3], uQh + aoff);
            ldsm_x4(qfl[0], qfl[1], qfl[2], qfl[3], uQl + aoff);
#pragma unroll
            for (int ntp = 0; ntp < 8; ntp++) {
                uint32_t boff = 2 * ((ntp * 16 + (lane & 15)) * PT + kc * 16 + (lane >> 4) * 8);
                uint32_t k0r, k1r, k2r, k3r;
                ldsm_x4(k0r, k1r, k2r, k3r, uK + boff);
                mma_f16(s[2*ntp],   qfh, k0r, k2r);
                mma_f16(s[2*ntp+1], qfh, k1r, k3r);
                mma_f16(s[2*ntp],   qfl, k0r, k2r);
                mma_f16(s[2*ntp+1], qfl, k1r, k3r);
            }
        }

        // scale 1/8
#pragma unroll
        for (int nt = 0; nt < 16; nt++) {
            s[nt][0] *= 0.125f; s[nt][1] *= 0.125f;
            s[nt][2] *= 0.125f; s[nt][3] *= 0.125f;
        }

        // causal mask (diagonal block only)
        if (kb == qb) {
            const int rl0 = w * 16 + trow;
#pragma unroll
            for (int nt = 0; nt < 16; nt++) {
                int c0 = nt * 8 + 2 * quad;
                if (c0 > rl0)     s[nt][0] = -1e30f;
                if (c0 + 1 > rl0) s[nt][1] = -1e30f;
                if (c0 > rl0 + 8)     s[nt][2] = -1e30f;
                if (c0 + 1 > rl0 + 8) s[nt][3] = -1e30f;
            }
        }

        // ---- online softmax ----
        float mx0 = -1e30f, mx1 = -1e30f;
#pragma unroll
        for (int nt = 0; nt < 16; nt++) {
            mx0 = fmaxf(mx0, fmaxf(s[nt][0], s[nt][1]));
            mx1 = fmaxf(mx1, fmaxf(s[nt][2], s[nt][3]));
        }
        mx0 = fmaxf(mx0, __shfl_xor_sync(0xffffffffu, mx0, 1));
        mx0 = fmaxf(mx0, __shfl_xor_sync(0xffffffffu, mx0, 2));
        mx1 = fmaxf(mx1, __shfl_xor_sync(0xffffffffu, mx1, 1));
        mx1 = fmaxf(mx1, __shfl_xor_sync(0xffffffffu, mx1, 2));
        float m0n = fmaxf(m0, mx0), m1n = fmaxf(m1, mx1);
        float al0 = __expf(m0 - m0n), al1 = __expf(m1 - m1n);
        m0 = m0n; m1 = m1n;

        float sum0 = 0.f, sum1 = 0.f;
#pragma unroll
        for (int nt = 0; nt < 16; nt++) {
            s[nt][0] = __expf(s[nt][0] - m0); sum0 += s[nt][0];
            s[nt][1] = __expf(s[nt][1] - m0); sum0 += s[nt][1];
            s[nt][2] = __expf(s[nt][2] - m1); sum1 += s[nt][2];
            s[nt][3] = __expf(s[nt][3] - m1); sum1 += s[nt][3];
        }
        sum0 += __shfl_xor_sync(0xffffffffu, sum0, 1);
        sum0 += __shfl_xor_sync(0xffffffffu, sum0, 2);
        sum1 += __shfl_xor_sync(0xffffffffu, sum1, 1);
        sum1 += __shfl_xor_sync(0xffffffffu, sum1, 2);
        l0 = l0 * al0 + sum0;
        l1 = l1 * al1 + sum1;

#pragma unroll
        for (int j = 0; j < 8; j++) {
            acc_o[j][0] *= al0; acc_o[j][1] *= al0;
            acc_o[j][2] *= al1; acc_o[j][3] *= al1;
        }

        // ---- O += P @ V : P split fp16 vs single V ----
#pragma unroll
        for (int kc = 0; kc < 8; kc++) {
            uint32_t pha[4], pla[4];
            pha[0] = pack_hi2(s[2*kc][0],   s[2*kc][1]);
            pha[1] = pack_hi2(s[2*kc][2],   s[2*kc][3]);
            pha[2] = pack_hi2(s[2*kc+1][0], s[2*kc+1][1]);
            pha[3] = pack_hi2(s[2*kc+1][2], s[2*kc+1][3]);
            pla[0] = pack_lo2(s[2*kc][0],   s[2*kc][1]);
            pla[1] = pack_lo2(s[2*kc][2],   s[2*kc][3]);
            pla[2] = pack_lo2(s[2*kc+1][0], s[2*kc+1][1]);
            pla[3] = pack_lo2(s[2*kc+1][2], s[2*kc+1][3]);
#pragma unroll
            for (int ht = 0; ht < 4; ht++) {
                uint32_t v0, v1, v2, v3;
                uint32_t off = 2 * ((kc * 16 + (lane & 15)) * PT + ht * 16 + (lane >> 4) * 8);
                ldsm_x4_t(v0, v1, v2, v3, uV + off);
                mma_f16(acc_o[2*ht],   pha, v0, v1);
                mma_f16(acc_o[2*ht+1], pha, v2, v3);
                mma_f16(acc_o[2*ht],   pla, v0, v1);
                mma_f16(acc_o[2*ht+1], pla, v2, v3);
            }
        }
    }

    // normalize and write split-fp16 output
    const float inv0 = 1.f / l0, inv1 = 1.f / l1;
    const size_t grow0 = (size_t)(b * SS + qb * 128 + w * 16 + trow);
    const size_t grow1 = grow0 + 8;
#pragma unroll
    for (int j = 0; j < 8; j++) {
        int c = h * HD + j * 8 + 2 * quad;
        float o00 = acc_o[j][0] * inv0, o01 = acc_o[j][1] * inv0;
        float o10 = acc_o[j][2] * inv1, o11 = acc_o[j][3] * inv1;
        *(uint32_t*)(oh + grow0 * DD + c) = pack_hi2(o00, o01);
        *(uint32_t*)(ol + grow0 * DD + c) = pack_lo2(o00, o01);
        *(uint32_t*)(oh + grow1 * DD + c) = pack_hi2(o10, o11);
        *(uint32_t*)(ol + grow1 * DD + c) = pack_lo2(o10, o11);
    }
}

// ---------------------------------------------------------------------------
extern "C" void kernel_launch(void* const* d_in, const int* in_sizes, int n_in,
                              void* d_out, int out_size)
{
    const float* x     = (const float*)d_in[0];
    const float* W_in  = (const float*)d_in[1];
    const float* b_in  = (const float*)d_in[2];
    const float* W_out = (const float*)d_in[3];
    const float* b_out = (const float*)d_in[4];
    float* out = (float*)d_out;

    __half *xh, *xl, *w1, *w2, *ph, *pl, *ah, *al;
    cudaGetSymbolAddress((void**)&xh, g_xh);
    cudaGetSymbolAddress((void**)&xl, g_xl);
    cudaGetSymbolAddress((void**)&w1, g_w1);
    cudaGetSymbolAddress((void**)&w2, g_w2);
    cudaGetSymbolAddress((void**)&ph, g_ph);
    cudaGetSymbolAddress((void**)&pl, g_pl);
    cudaGetSymbolAddress((void**)&ah, g_ah);
    cudaGetSymbolAddress((void**)&al, g_al);

    const int gemm_smem = 2 * STG * (int)sizeof(__half);   // 61440
    cudaFuncSetAttribute(gemm_mma, cudaFuncAttributeMaxDynamicSharedMemorySize, gemm_smem);
    cudaFuncSetAttribute(attn_mma, cudaFuncAttributeMaxDynamicSharedMemorySize, A_SMEM);

    // prep
    split_fp16<<<(BS * DD / 4 + 255) / 256, 256>>>(x, xh, xl, BS * DD / 4);
    transpose_fp16<<<dim3(3 * DD / 32, DD / 32), dim3(32, 8)>>>(W_in, w1, DD, 3 * DD);
    transpose_fp16<<<dim3(DD / 32, DD / 32), dim3(32, 8)>>>(W_out, w2, DD, DD);

    // 1) QKV projection -> split fp16 proj
    gemm_mma<<<dim3(3 * DD / 128, BS / 128), 256, gemm_smem>>>(
        xh, xl, w1, b_in, nullptr, ph, pl, BS, 3 * DD, DD);

    // 2) attention
    {
        dim3 grid(SS / 128, BB * HH);
        attn_mma<<<grid, 256, A_SMEM>>>(ph, pl, ah, al);
    }

    // 3) output projection -> fp32 out
    gemm_mma<<<dim3(DD / 128, BS / 128), 256, gemm_smem>>>(
        ah, al, w2, b_out, out, nullptr, nullptr, BS, DD, DD);
}

// round 10
// speedup vs baseline: 1.8755x; 1.2960x over previous
#include <cuda_runtime.h>
#include <cuda_fp16.h>
#include <cstdint>

// Problem constants
#define BB   4
#define SS   2048
#define DD   1024
#define HH   16
#define HD   64
#define BS   (BB*SS)        // 8192

__device__ __forceinline__ uint32_t smem_u32(const void* p) {
    uint32_t a;
    asm("{ .reg .u64 t; cvta.to.shared.u64 t, %1; cvt.u32.u64 %0, t; }" : "=r"(a) : "l"(p));
    return a;
}
__device__ __forceinline__ void cp16(uint32_t dst, const void* src) {
    asm volatile("cp.async.cg.shared.global [%0], [%1], 16;" :: "r"(dst), "l"(src));
}
#define CP_COMMIT() asm volatile("cp.async.commit_group;" ::: "memory")
#define CP_WAIT0()  asm volatile("cp.async.wait_group 0;" ::: "memory")

// ---------------------------------------------------------------------------
// Scratch (device globals)
//   GEMM A-sides: single fp16.  Attention: Q split hi+lo, K/V single, P split.
// ---------------------------------------------------------------------------
__device__ __half g_x16[(size_t)BS * DD];      // x fp16
__device__ __half g_w1[(size_t)(3*DD) * DD];   // W_in^T  [3072,1024] fp16
__device__ __half g_w2[(size_t)DD * DD];       // W_out^T [1024,1024] fp16
__device__ __half g_ph[(size_t)BS * 3 * DD];   // proj hi (k|q|v)
__device__ __half g_pl[(size_t)BS * 3 * DD];   // proj lo (read for Q only)
__device__ __half g_ah[(size_t)BS * DD];       // attention out fp16

// ---------------------------------------------------------------------------
// Prep kernels
// ---------------------------------------------------------------------------
__global__ __launch_bounds__(256) void conv_fp16(
    const float* __restrict__ src, __half* __restrict__ dst, int n4)
{
    int i = blockIdx.x * 256 + threadIdx.x;
    if (i >= n4) return;
    float4 v = ((const float4*)src)[i];
    ((__half2*)dst)[i*2+0] = __floats2half2_rn(v.x, v.y);
    ((__half2*)dst)[i*2+1] = __floats2half2_rn(v.z, v.w);
}

__global__ __launch_bounds__(256) void transpose_fp16(
    const float* __restrict__ W, __half* __restrict__ wt, int K, int N)
{
    __shared__ float tile[32][33];
    int k0 = blockIdx.y * 32, n0 = blockIdx.x * 32;
    int tx = threadIdx.x, ty = threadIdx.y;   // 32 x 8
#pragma unroll
    for (int j = 0; j < 32; j += 8)
        tile[ty + j][tx] = W[(size_t)(k0 + ty + j) * N + n0 + tx];
    __syncthreads();
#pragma unroll
    for (int j = 0; j < 32; j += 8)
        wt[(size_t)(n0 + ty + j) * K + k0 + tx] = __float2half_rn(tile[tx][ty + j]);
}

// ---------------------------------------------------------------------------
// mma.sync helpers (fp16 inputs, fp32 accumulate)
// ---------------------------------------------------------------------------
__device__ __forceinline__ void ldsm_x4(uint32_t& r0, uint32_t& r1, uint32_t& r2, uint32_t& r3,
                                        uint32_t addr) {
    asm volatile("ldmatrix.sync.aligned.m8n8.x4.shared.b16 {%0,%1,%2,%3}, [%4];"
                 : "=r"(r0), "=r"(r1), "=r"(r2), "=r"(r3) : "r"(addr));
}
__device__ __forceinline__ void ldsm_x4_t(uint32_t& r0, uint32_t& r1, uint32_t& r2, uint32_t& r3,
                                          uint32_t addr) {
    asm volatile("ldmatrix.sync.aligned.m8n8.x4.trans.shared.b16 {%0,%1,%2,%3}, [%4];"
                 : "=r"(r0), "=r"(r1), "=r"(r2), "=r"(r3) : "r"(addr));
}
__device__ __forceinline__ void mma_f16(float* d, const uint32_t* a, uint32_t b0, uint32_t b1) {
    asm volatile(
        "mma.sync.aligned.m16n8k16.row.col.f32.f16.f16.f32 "
        "{%0,%1,%2,%3}, {%4,%5,%6,%7}, {%8,%9}, {%0,%1,%2,%3};"
        : "+f"(d[0]), "+f"(d[1]), "+f"(d[2]), "+f"(d[3])
        : "r"(a[0]), "r"(a[1]), "r"(a[2]), "r"(a[3]), "r"(b0), "r"(b1));
}
__device__ __forceinline__ uint32_t pack_hi2(float x, float y) {
    __half2 t = __floats2half2_rn(x, y);
    return *(uint32_t*)&t;
}
__device__ __forceinline__ uint32_t pack_lo2(float x, float y) {
    float hx = __half2float(__float2half_rn(x));
    float hy = __half2float(__float2half_rn(y));
    __half2 t = __floats2half2_rn(x - hx, y - hy);
    return *(uint32_t*)&t;
}

// ---------------------------------------------------------------------------
// GEMM on mma.sync: C = A @ B^T + bias, both single fp16.
// 128x128 tile, BK=32, cp.async double buffer, 2 CTAs/SM.
// ---------------------------------------------------------------------------
#define PA 40
#define STG (2 * 128 * PA)   // fp16 elems per stage (A | B)

__global__ __launch_bounds__(256, 2) void gemm_mma(
    const __half* __restrict__ Aa, const __half* __restrict__ Bw,
    const float* __restrict__ bias,
    float* __restrict__ C, __half* __restrict__ Ch, __half* __restrict__ Cl,
    int M, int N, int K)
{
    extern __shared__ __half sg[];   // 2 * STG
    const uint32_t uBase = smem_u32(sg);

    const int tid  = threadIdx.x;
    const int wid  = tid >> 5;
    const int lane = tid & 31;
    const int wrow = wid & 3;
    const int wcol = wid >> 2;
    const int m0 = blockIdx.y * 128;
    const int n0 = blockIdx.x * 128;

    const int a_row = wrow * 32 + (lane & 7) + ((lane >> 3) & 1) * 8;
    const int a_k   = (lane >> 4) * 8;
    const int b_row = wcol * 64 + (lane >> 4) * 8 + (lane & 7);
    const int b_k   = ((lane >> 3) & 1) * 8;

    const __half* gsrc[2] = { Aa + (size_t)m0 * K, Bw + (size_t)n0 * K };

    auto load_stage = [&](int kc, int buf) {
        const int k0 = kc << 5;
        const uint32_t sb = uBase + buf * (STG * 2);
#pragma unroll
        for (int v = tid; v < 1024; v += 256) {
            int t = v >> 9, idx = v & 511;
            int r = idx >> 2, c = idx & 3;
            cp16(sb + (t * (128 * PA) + r * PA + c * 8) * 2,
                 gsrc[t] + (size_t)r * K + k0 + c * 8);
        }
    };

    float acc[2][8][4];
#pragma unroll
    for (int i = 0; i < 2; i++)
#pragma unroll
        for (int j = 0; j < 8; j++)
#pragma unroll
            for (int v = 0; v < 4; v++) acc[i][j][v] = 0.f;

    const int nchunks = K >> 5;
    load_stage(0, 0);
    CP_COMMIT();

    for (int kc = 0; kc < nchunks; ++kc) {
        const int buf = kc & 1;
        CP_WAIT0();
        __syncthreads();
        if (kc + 1 < nchunks) {
            load_stage(kc + 1, buf ^ 1);
            CP_COMMIT();
        }
        const uint32_t s0 = uBase + buf * (STG * 2);
        const uint32_t tA = s0;
        const uint32_t tB = s0 + (128 * PA) * 2;

#pragma unroll
        for (int ks = 0; ks < 2; ks++) {
            uint32_t ah[2][4];
#pragma unroll
            for (int mi = 0; mi < 2; mi++) {
                uint32_t off = 2 * ((a_row + mi * 16) * PA + ks * 16 + a_k);
                ldsm_x4(ah[mi][0], ah[mi][1], ah[mi][2], ah[mi][3], tA + off);
            }
#pragma unroll
            for (int j = 0; j < 4; j++) {
                uint32_t off = 2 * ((b_row + j * 16) * PA + ks * 16 + b_k);
                uint32_t b0, b1, b2, b3;
                ldsm_x4(b0, b1, b2, b3, tB + off);
#pragma unroll
                for (int mi = 0; mi < 2; mi++) {
                    mma_f16(acc[mi][2*j],   ah[mi], b0, b1);
                    mma_f16(acc[mi][2*j+1], ah[mi], b2, b3);
                }
            }
        }
        __syncthreads();
    }

    const int row0 = m0 + wrow * 32 + (lane >> 2);
    const int colb = n0 + wcol * 64 + (lane & 3) * 2;
#pragma unroll
    for (int mi = 0; mi < 2; mi++) {
#pragma unroll
        for (int nj = 0; nj < 8; nj++) {
            int c = colb + nj * 8;
            float2 bv = *(const float2*)(bias + c);
            float o00 = acc[mi][nj][0] + bv.x, o01 = acc[mi][nj][1] + bv.y;
            float o10 = acc[mi][nj][2] + bv.x, o11 = acc[mi][nj][3] + bv.y;
            size_t r0o = (size_t)(row0 + mi * 16) * N + c;
            size_t r1o = (size_t)(row0 + mi * 16 + 8) * N + c;
            if (Ch) {
                *(uint32_t*)(Ch + r0o) = pack_hi2(o00, o01);
                *(uint32_t*)(Cl + r0o) = pack_lo2(o00, o01);
                *(uint32_t*)(Ch + r1o) = pack_hi2(o10, o11);
                *(uint32_t*)(Cl + r1o) = pack_lo2(o10, o11);
            } else {
                *(float2*)(C + r0o) = make_float2(o00, o01);
                *(float2*)(C + r1o) = make_float2(o10, o11);
            }
        }
    }
}

// ---------------------------------------------------------------------------
// Flash-attention: Q split fp16 (hi+lo), K and V single fp16,
// P split fp16 from registers. 128-row tiles, cp.async double-buffered K/V.
// Output: single fp16 (GEMM2 A-side is unsplit).
// ---------------------------------------------------------------------------
#define PT 72
#define AT (128 * PT)      // one tile in fp16 elems (9216)
// smem: Qh | Ql | stage0 (K|V) | stage1 (K|V) = 6 tiles
#define A_SMEM (6 * AT * 2)   // 110592 B

__global__ __launch_bounds__(256) void attn_mma(
    const __half* __restrict__ ph, const __half* __restrict__ pl,
    __half* __restrict__ oh)
{
    extern __shared__ __half sb[];
    const uint32_t uBase = smem_u32(sb);
    const uint32_t uQh = uBase, uQl = uBase + AT * 2;

    const int qb = gridDim.x - 1 - blockIdx.x;   // heavy blocks first
    const int bh = blockIdx.y;
    const int b = bh / HH, h = bh % HH;
    const int tid = threadIdx.x, w = tid >> 5, lane = tid & 31;
    const int quad = lane & 3, trow = lane >> 2;

    const size_t rowstride = 3 * DD;
    const size_t rbase = (size_t)b * SS * rowstride;
    const int koff = h * HD, qoff = DD + h * HD, voff = 2 * DD + h * HD;

    // Q copy (hi+lo): 2 tiles x 128 rows x 8 uint4
#pragma unroll
    for (int i = tid; i < 2048; i += 256) {
        int t = i >> 10, idx = i & 1023;
        int r = idx >> 3, c = idx & 7;
        const __half* src = (t ? pl : ph) + rbase + (size_t)(qb * 128 + r) * rowstride + qoff + c * 8;
        cp16(uBase + (t * AT + r * PT + c * 8) * 2, src);
    }

    // KV loader: K and V tiles (hi only)
    auto load_kv = [&](int kb, int buf) {
        const uint32_t sbs = uBase + (2 * AT + buf * 2 * AT) * 2;
#pragma unroll
        for (int i = tid; i < 2048; i += 256) {
            int t = i >> 10, idx = i & 1023;
            int r = idx >> 3, c = idx & 7;
            int off = t ? voff : koff;
            cp16(sbs + (t * AT + r * PT + c * 8) * 2,
                 ph + rbase + (size_t)(kb * 128 + r) * rowstride + off + c * 8);
        }
    };

    load_kv(0, 0);
    CP_COMMIT();

    float acc_o[8][4];
#pragma unroll
    for (int j = 0; j < 8; j++)
#pragma unroll
        for (int v = 0; v < 4; v++) acc_o[j][v] = 0.f;
    float m0 = -1e30f, m1 = -1e30f, l0 = 0.f, l1 = 0.f;

    for (int kb = 0; kb <= qb; ++kb) {
        const int buf = kb & 1;
        CP_WAIT0();
        __syncthreads();
        if (kb < qb) {
            load_kv(kb + 1, buf ^ 1);
            CP_COMMIT();
        }
        const uint32_t s0 = uBase + (2 * AT + buf * 2 * AT) * 2;
        const uint32_t uK = s0, uV = s0 + AT * 2;

        // ---- S = Q @ K^T : Q hi+lo vs single K ----
        float s[16][4];
#pragma unroll
        for (int j = 0; j < 16; j++)
#pragma unroll
            for (int v = 0; v < 4; v++) s[j][v] = 0.f;

#pragma unroll
        for (int kc = 0; kc < 4; kc++) {
            uint32_t qfh[4], qfl[4];
            uint32_t aoff = 2 * ((w * 16 + (lane & 15)) * PT + kc * 16 + (lane >> 4) * 8);
            ldsm_x4(qfh[0], qfh[1], qfh[2], qfh[3], uQh + aoff);
            ldsm_x4(qfl[0], qfl[1], qfl[2], qfl[3], uQl + aoff);
#pragma unroll
            for (int ntp = 0; ntp < 8; ntp++) {
                uint32_t boff = 2 * ((ntp * 16 + (lane & 15)) * PT + kc * 16 + (lane >> 4) * 8);
                uint32_t k0r, k1r, k2r, k3r;
                ldsm_x4(k0r, k1r, k2r, k3r, uK + boff);
                mma_f16(s[2*ntp],   qfh, k0r, k2r);
                mma_f16(s[2*ntp+1], qfh, k1r, k3r);
                mma_f16(s[2*ntp],   qfl, k0r, k2r);
                mma_f16(s[2*ntp+1], qfl, k1r, k3r);
            }
        }

        // scale 1/8
#pragma unroll
        for (int nt = 0; nt < 16; nt++) {
            s[nt][0] *= 0.125f; s[nt][1] *= 0.125f;
            s[nt][2] *= 0.125f; s[nt][3] *= 0.125f;
        }

        // causal mask (diagonal block only)
        if (kb == qb) {
            const int rl0 = w * 16 + trow;
#pragma unroll
            for (int nt = 0; nt < 16; nt++) {
                int c0 = nt * 8 + 2 * quad;
                if (c0 > rl0)     s[nt][0] = -1e30f;
                if (c0 + 1 > rl0) s[nt][1] = -1e30f;
                if (c0 > rl0 + 8)     s[nt][2] = -1e30f;
                if (c0 + 1 > rl0 + 8) s[nt][3] = -1e30f;
            }
        }

        // ---- online softmax ----
        float mx0 = -1e30f, mx1 = -1e30f;
#pragma unroll
        for (int nt = 0; nt < 16; nt++) {
            mx0 = fmaxf(mx0, fmaxf(s[nt][0], s[nt][1]));
            mx1 = fmaxf(mx1, fmaxf(s[nt][2], s[nt][3]));
        }
        mx0 = fmaxf(mx0, __shfl_xor_sync(0xffffffffu, mx0, 1));
        mx0 = fmaxf(mx0, __shfl_xor_sync(0xffffffffu, mx0, 2));
        mx1 = fmaxf(mx1, __shfl_xor_sync(0xffffffffu, mx1, 1));
        mx1 = fmaxf(mx1, __shfl_xor_sync(0xffffffffu, mx1, 2));
        float m0n = fmaxf(m0, mx0), m1n = fmaxf(m1, mx1);
        float al0 = __expf(m0 - m0n), al1 = __expf(m1 - m1n);
        m0 = m0n; m1 = m1n;

        float sum0 = 0.f, sum1 = 0.f;
#pragma unroll
        for (int nt = 0; nt < 16; nt++) {
            s[nt][0] = __expf(s[nt][0] - m0); sum0 += s[nt][0];
            s[nt][1] = __expf(s[nt][1] - m0); sum0 += s[nt][1];
            s[nt][2] = __expf(s[nt][2] - m1); sum1 += s[nt][2];
            s[nt][3] = __expf(s[nt][3] - m1); sum1 += s[nt][3];
        }
        sum0 += __shfl_xor_sync(0xffffffffu, sum0, 1);
        sum0 += __shfl_xor_sync(0xffffffffu, sum0, 2);
        sum1 += __shfl_xor_sync(0xffffffffu, sum1, 1);
        sum1 += __shfl_xor_sync(0xffffffffu, sum1, 2);
        l0 = l0 * al0 + sum0;
        l1 = l1 * al1 + sum1;

#pragma unroll
        for (int j = 0; j < 8; j++) {
            acc_o[j][0] *= al0; acc_o[j][1] *= al0;
            acc_o[j][2] *= al1; acc_o[j][3] *= al1;
        }

        // ---- O += P @ V : P split fp16 vs single V ----
#pragma unroll
        for (int kc = 0; kc < 8; kc++) {
            uint32_t pha[4], pla[4];
            pha[0] = pack_hi2(s[2*kc][0],   s[2*kc][1]);
            pha[1] = pack_hi2(s[2*kc][2],   s[2*kc][3]);
            pha[2] = pack_hi2(s[2*kc+1][0], s[2*kc+1][1]);
            pha[3] = pack_hi2(s[2*kc+1][2], s[2*kc+1][3]);
            pla[0] = pack_lo2(s[2*kc][0],   s[2*kc][1]);
            pla[1] = pack_lo2(s[2*kc][2],   s[2*kc][3]);
            pla[2] = pack_lo2(s[2*kc+1][0], s[2*kc+1][1]);
            pla[3] = pack_lo2(s[2*kc+1][2], s[2*kc+1][3]);
#pragma unroll
            for (int ht = 0; ht < 4; ht++) {
                uint32_t v0, v1, v2, v3;
                uint32_t off = 2 * ((kc * 16 + (lane & 15)) * PT + ht * 16 + (lane >> 4) * 8);
                ldsm_x4_t(v0, v1, v2, v3, uV + off);
                mma_f16(acc_o[2*ht],   pha, v0, v1);
                mma_f16(acc_o[2*ht+1], pha, v2, v3);
                mma_f16(acc_o[2*ht],   pla, v0, v1);
                mma_f16(acc_o[2*ht+1], pla, v2, v3);
            }
        }
    }

    // normalize and write fp16 output (hi only — GEMM2 A unsplit)
    const float inv0 = 1.f / l0, inv1 = 1.f / l1;
    const size_t grow0 = (size_t)(b * SS + qb * 128 + w * 16 + trow);
    const size_t grow1 = grow0 + 8;
#pragma unroll
    for (int j = 0; j < 8; j++) {
        int c = h * HD + j * 8 + 2 * quad;
        *(uint32_t*)(oh + grow0 * DD + c) = pack_hi2(acc_o[j][0] * inv0, acc_o[j][1] * inv0);
        *(uint32_t*)(oh + grow1 * DD + c) = pack_hi2(acc_o[j][2] * inv1, acc_o[j][3] * inv1);
    }
}

// ---------------------------------------------------------------------------
extern "C" void kernel_launch(void* const* d_in, const int* in_sizes, int n_in,
                              void* d_out, int out_size)
{
    const float* x     = (const float*)d_in[0];
    const float* W_in  = (const float*)d_in[1];
    const float* b_in  = (const float*)d_in[2];
    const float* W_out = (const float*)d_in[3];
    const float* b_out = (const float*)d_in[4];
    float* out = (float*)d_out;

    __half *x16, *w1, *w2, *ph, *pl, *ah;
    cudaGetSymbolAddress((void**)&x16, g_x16);
    cudaGetSymbolAddress((void**)&w1, g_w1);
    cudaGetSymbolAddress((void**)&w2, g_w2);
    cudaGetSymbolAddress((void**)&ph, g_ph);
    cudaGetSymbolAddress((void**)&pl, g_pl);
    cudaGetSymbolAddress((void**)&ah, g_ah);

    const int gemm_smem = 2 * STG * (int)sizeof(__half);   // 40960
    cudaFuncSetAttribute(gemm_mma, cudaFuncAttributeMaxDynamicSharedMemorySize, gemm_smem);
    cudaFuncSetAttribute(attn_mma, cudaFuncAttributeMaxDynamicSharedMemorySize, A_SMEM);

    // prep
    conv_fp16<<<(BS * DD / 4 + 255) / 256, 256>>>(x, x16, BS * DD / 4);
    transpose_fp16<<<dim3(3 * DD / 32, DD / 32), dim3(32, 8)>>>(W_in, w1, DD, 3 * DD);
    transpose_fp16<<<dim3(DD / 32, DD / 32), dim3(32, 8)>>>(W_out, w2, DD, DD);

    // 1) QKV projection (fp16 x fp16) -> split fp16 proj
    gemm_mma<<<dim3(3 * DD / 128, BS / 128), 256, gemm_smem>>>(
        x16, w1, b_in, nullptr, ph, pl, BS, 3 * DD, DD);

    // 2) attention (Q split, K/V single, P split) -> fp16 out
    {
        dim3 grid(SS / 128, BB * HH);
        attn_mma<<<grid, 256, A_SMEM>>>(ph, pl, ah);
    }

    // 3) output projection (fp16 x fp16) -> fp32 out
    gemm_mma<<<dim3(DD / 128, BS / 128), 256, gemm_smem>>>(
        ah, w2, b_out, out, nullptr, nullptr, BS, DD, DD);
}